// round 8
// baseline (speedup 1.0000x reference)
#include <cuda_runtime.h>

#define NXg 512
#define NYg 512
#define NTg 300
#define NCELL (NXg * NYg)

#define TI 64                     // tile rows per block
#define TJ 32                     // tile cols per block
#define KSTEP 10
#define NLAUNCH (NTg / KSTEP)     // 30
#define RI (TI + 2 * KSTEP)       // 84 region rows
#define RJ (TJ + 2 * KSTEP)       // 52 region cols (13 float4 groups)
#define NGRP (RJ / 4)             // 13 column groups
#define NPAIR (RI / 2)            // 42 row pairs
#define PITCH 68                  // floats per smem row (16B aligned, bank-shifted)
#define SROWS (RI + 2)            // 86 rows incl guard top/bottom
#define SSZ (SROWS * PITCH)       // 5848 floats per level
#define COL0 4                    // smem float offset of region col 0 (guards at 3 / 56)
#define NTHR (NGRP * NPAIR)       // 546 threads

// Ping-pong pairs across launches.
__device__ float g_u1a[NCELL];
__device__ float g_u2a[NCELL];
__device__ float g_u1b[NCELL];
__device__ float g_u2b[NCELL];

__global__ void wave_zero_kernel() {
    int idx = blockIdx.x * blockDim.x + threadIdx.x;
    if (idx < NCELL) {
        g_u1a[idx] = 0.0f;
        g_u2a[idx] = 0.0f;
    }
}

// PML ramp: b_vals[k] = 0.5 * (k/20)^3, k in [0,20]
__device__ __forceinline__ float pml_ramp(int k) {
    float t = (float)k * (1.0f / 20.0f);
    return 0.5f * t * t * t;
}

__device__ __forceinline__ float pml_b(int gi, int gj) {
    float bx = 0.0f, by = 0.0f;
    if (gi <= 20) bx = pml_ramp(20 - gi);
    else if (gi >= NXg - 22 && gi <= NXg - 2) bx = pml_ramp(gi - (NXg - 22));
    if (gj <= 20) by = pml_ramp(20 - gj);
    else if (gj >= NYg - 22 && gj <= NYg - 2) by = pml_ramp(gj - (NYg - 22));
    return sqrtf(bx * bx + by * by);
}

__global__ void __launch_bounds__(NTHR)
wave_tb_kernel(const float* __restrict__ c2,
               const float* __restrict__ msrc,
               const float* __restrict__ xsrc,
               const float* __restrict__ rd1,   // u at t0
               const float* __restrict__ rd2,   // u at t0-1
               float* __restrict__ wr1,
               float* __restrict__ wr2,
               float* __restrict__ d_final,
               int t0, int isLast) {
    __shared__ __align__(16) float s0[SSZ];
    __shared__ __align__(16) float s1[SSZ];
    __shared__ float sX[KSTEP];

    const int tx = threadIdx.x;            // 0..12  column group
    const int ty = threadIdx.y;            // 0..41  row pair
    const int tid = ty * NGRP + tx;

    const int gi0 = blockIdx.y * TI;
    const int gj0 = blockIdx.x * TJ;
    const int ri0 = gi0 - KSTEP;
    const int rj0 = gj0 - KSTEP;
    const int r0 = 2 * ty;                              // first owned region row
    const int base0 = (r0 + 1) * PITCH + COL0 + 4 * tx; // smem idx, row0 lane0
    const int base1 = base0 + PITCH;

    if (tid < KSTEP) sX[tid] = xsrc[t0 + tid];

    // Zero both levels incl. guards (guards stay 0; out-of-domain rewritten 0).
    for (int k = tid; k < SSZ; k += NTHR) { s0[k] = 0.0f; s1[k] = 0.0f; }

    // ---- Load 2x4 cell block: fields + coefficients into registers ----
    float cur[2][4], old[2][4];
    float cP4[2][4], cQ[2][4], cRc[2][4], cSb[2][4];
    #pragma unroll
    for (int r = 0; r < 2; ++r) {
        int gi = ri0 + r0 + r;
        #pragma unroll
        for (int i = 0; i < 4; ++i) {
            int gj = rj0 + 4 * tx + i;
            bool in = ((unsigned)gi < NXg) && ((unsigned)gj < NYg);
            float u1 = 0.0f, u2 = 0.0f, P4 = 0.0f, Qv = 0.0f, Rcv = 0.0f, Sbv = 0.0f;
            if (in) {
                int g = gi * NYg + gj;
                u1 = rd1[g];
                u2 = rd2[g];
                float b = pml_b(gi, gj);
                float rb = 1.0f / (4.0f + b);
                float c2v = c2[g];
                P4 = (8.0f - 4.0f * c2v) * rb;   // center coeff
                Qv = (4.0f - b) * rb;            // old-level coeff
                Rcv = c2v * rb;                  // 4-neighbor-sum coeff
                Sbv = msrc[g] * rb;              // source coeff
            }
            cur[r][i] = u1; old[r][i] = u2;
            cP4[r][i] = P4; cQ[r][i] = Qv; cRc[r][i] = Rcv; cSb[r][i] = Sbv;
        }
    }
    __syncthreads();    // zero-fill complete before field STS
    *(float4*)(s0 + base0) = make_float4(cur[0][0], cur[0][1], cur[0][2], cur[0][3]);
    *(float4*)(s0 + base1) = make_float4(cur[1][0], cur[1][1], cur[1][2], cur[1][3]);
    __syncthreads();

    // ---- KSTEP time steps, fully unrolled, branch-free ----
    #pragma unroll
    for (int s = 0; s < KSTEP; ++s) {
        const float* sc = (s & 1) ? s1 : s0;
        float* sn = (s & 1) ? s0 : s1;
        const float xi = sX[s];

        float4 up = *(const float4*)(sc + base0 - PITCH);
        float4 dn = *(const float4*)(sc + base1 + PITCH);
        float lf0 = sc[base0 - 1], rt0 = sc[base0 + 4];
        float lf1 = sc[base1 - 1], rt1 = sc[base1 + 4];

        // Neighbor sums (row0 uses row1 regs as down; row1 uses row0 regs as up)
        float n0[4], n1[4];
        n0[0] = (up.x + cur[1][0]) + (lf0 + cur[0][1]);
        n0[1] = (up.y + cur[1][1]) + (cur[0][0] + cur[0][2]);
        n0[2] = (up.z + cur[1][2]) + (cur[0][1] + cur[0][3]);
        n0[3] = (up.w + cur[1][3]) + (cur[0][2] + rt0);
        n1[0] = (cur[0][0] + dn.x) + (lf1 + cur[1][1]);
        n1[1] = (cur[0][1] + dn.y) + (cur[1][0] + cur[1][2]);
        n1[2] = (cur[0][2] + dn.z) + (cur[1][1] + cur[1][3]);
        n1[3] = (cur[0][3] + dn.w) + (cur[1][2] + rt1);

        float v0[4], v1[4];
        #pragma unroll
        for (int i = 0; i < 4; ++i) {
            float a = cP4[0][i] * cur[0][i];
            a = fmaf(-cQ[0][i], old[0][i], a);
            a = fmaf(cRc[0][i], n0[i], a);
            v0[i] = fmaf(cSb[0][i], xi, a);
            float b = cP4[1][i] * cur[1][i];
            b = fmaf(-cQ[1][i], old[1][i], b);
            b = fmaf(cRc[1][i], n1[i], b);
            v1[i] = fmaf(cSb[1][i], xi, b);
        }

        *(float4*)(sn + base0) = make_float4(v0[0], v0[1], v0[2], v0[3]);
        *(float4*)(sn + base1) = make_float4(v1[0], v1[1], v1[2], v1[3]);

        #pragma unroll
        for (int i = 0; i < 4; ++i) {
            old[0][i] = cur[0][i]; cur[0][i] = v0[i];
            old[1][i] = cur[1][i]; cur[1][i] = v1[i];
        }
        __syncthreads();
    }

    // cur = t0+KSTEP, old = t0+KSTEP-1. Write back the 64x32 tile
    // (region rows [KSTEP, KSTEP+TI), cols [KSTEP, KSTEP+TJ)).
    #pragma unroll
    for (int r = 0; r < 2; ++r) {
        int rr = r0 + r;
        if (rr >= KSTEP && rr < KSTEP + TI) {
            int gi = ri0 + rr;
            #pragma unroll
            for (int i = 0; i < 4; ++i) {
                int cc = 4 * tx + i;
                if (cc >= KSTEP && cc < KSTEP + TJ) {
                    int g = gi * NYg + (rj0 + cc);
                    if (isLast) {
                        d_final[g] = cur[r][i];
                    } else {
                        wr1[g] = cur[r][i];
                        wr2[g] = old[r][i];
                    }
                }
            }
        }
    }
}

extern "C" void kernel_launch(void* const* d_in, const int* in_sizes, int n_in,
                              void* d_out, int out_size) {
    const float* x    = (const float*)d_in[0];   // (300,)
    const float* c2   = (const float*)d_in[1];   // (512,512)
    const float* msrc = (const float*)d_in[2];   // (512,512)
    float* out = (float*)d_out;

    float *u1a, *u2a, *u1b, *u2b;
    cudaGetSymbolAddress((void**)&u1a, g_u1a);
    cudaGetSymbolAddress((void**)&u2a, g_u2a);
    cudaGetSymbolAddress((void**)&u1b, g_u1b);
    cudaGetSymbolAddress((void**)&u2b, g_u2b);

    wave_zero_kernel<<<NCELL / 256, 256>>>();

    dim3 grd(NYg / TJ, NXg / TI);   // (16, 8) = 128 blocks, 1 per SM
    dim3 blk(NGRP, NPAIR);          // (13, 42) = 546 threads
    for (int l = 0; l < NLAUNCH; ++l) {
        bool even = (l & 1) == 0;
        const float* r1 = even ? u1a : u1b;
        const float* r2 = even ? u2a : u2b;
        float* w1 = even ? u1b : u1a;
        float* w2 = even ? u2b : u2a;
        wave_tb_kernel<<<grd, blk>>>(c2, msrc, x, r1, r2, w1, w2, out,
                                     l * KSTEP, l == NLAUNCH - 1 ? 1 : 0);
    }
}

// round 9
// speedup vs baseline: 1.3463x; 1.3463x over previous
#include <cuda_runtime.h>

#define NXg 512
#define NYg 512
#define NTg 300
#define NCELL (NXg * NYg)

#define TI 64                     // tile rows per block
#define TJ 32                     // tile cols per block
#define KSTEP 10
#define NPHASE (NTg / KSTEP)      // 30
#define RI (TI + 2 * KSTEP)       // 84 region rows
#define RJ (TJ + 2 * KSTEP)       // 52 region cols (13 float4 groups)
#define NGRP (RJ / 4)             // 13 column groups
#define NPAIR (RI / 2)            // 42 row pairs
#define PITCH 68                  // floats per smem row (16B aligned, bank-shifted)
#define SROWS (RI + 2)            // 86 rows incl guard top/bottom
#define SSZ (SROWS * PITCH)       // 5848 floats per level
#define COL0 4                    // smem float offset of region col 0
#define NTHR (NGRP * NPAIR)       // 546 threads
#define NBLK 128                  // (16 x 8) blocks, 1 per SM, all resident

// Ping-pong pairs across phases + grid-barrier counter.
__device__ float g_u1a[NCELL];
__device__ float g_u2a[NCELL];
__device__ float g_u1b[NCELL];
__device__ float g_u2b[NCELL];
__device__ unsigned g_bar;

__global__ void wave_zero_kernel() {
    int idx = blockIdx.x * blockDim.x + threadIdx.x;
    if (idx == 0) g_bar = 0u;
    if (idx < NCELL) {
        g_u1a[idx] = 0.0f;
        g_u2a[idx] = 0.0f;
    }
}

// PML ramp: b_vals[k] = 0.5 * (k/20)^3, k in [0,20]
__device__ __forceinline__ float pml_ramp(int k) {
    float t = (float)k * (1.0f / 20.0f);
    return 0.5f * t * t * t;
}

__device__ __forceinline__ float pml_b(int gi, int gj) {
    float bx = 0.0f, by = 0.0f;
    if (gi <= 20) bx = pml_ramp(20 - gi);
    else if (gi >= NXg - 22 && gi <= NXg - 2) bx = pml_ramp(gi - (NXg - 22));
    if (gj <= 20) by = pml_ramp(20 - gj);
    else if (gj >= NYg - 22 && gj <= NYg - 2) by = pml_ramp(gj - (NYg - 22));
    return sqrtf(bx * bx + by * by);
}

__global__ void __launch_bounds__(NTHR)
wave_persist_kernel(const float* __restrict__ c2,
                    const float* __restrict__ msrc,
                    const float* __restrict__ xsrc,
                    float* __restrict__ d_final) {
    __shared__ __align__(16) float s0[SSZ];
    __shared__ __align__(16) float s1[SSZ];
    __shared__ float sX[KSTEP];

    const int tx = threadIdx.x;            // 0..12  column group
    const int ty = threadIdx.y;            // 0..41  row pair
    const int tid = ty * NGRP + tx;

    const int gi0 = blockIdx.y * TI;
    const int gj0 = blockIdx.x * TJ;
    const int ri0 = gi0 - KSTEP;
    const int rj0 = gj0 - KSTEP;
    const int r0 = 2 * ty;                              // first owned region row
    const int base0 = (r0 + 1) * PITCH + COL0 + 4 * tx;
    const int base1 = base0 + PITCH;

    // Zero both smem levels incl. guards (guards stay 0 forever).
    for (int k = tid; k < SSZ; k += NTHR) { s0[k] = 0.0f; s1[k] = 0.0f; }

    // ---- One-time: coefficients + cell metadata into registers ----
    float cur[2][4], old[2][4];
    float cP4[2][4], cQ[2][4], cRc[2][4], cSb[2][4];
    int gidx[2][4];          // global index (valid only if inDom)
    bool inDom[2][4], inTile[2][4];
    #pragma unroll
    for (int r = 0; r < 2; ++r) {
        int rr = r0 + r;
        int gi = ri0 + rr;
        #pragma unroll
        for (int i = 0; i < 4; ++i) {
            int cc = 4 * tx + i;
            int gj = rj0 + cc;
            bool in = ((unsigned)gi < NXg) && ((unsigned)gj < NYg);
            inDom[r][i] = in;
            inTile[r][i] = (rr >= KSTEP) && (rr < KSTEP + TI) &&
                           (cc >= KSTEP) && (cc < KSTEP + TJ);
            int g = in ? (gi * NYg + gj) : 0;
            gidx[r][i] = g;
            float P4 = 0.0f, Qv = 0.0f, Rcv = 0.0f, Sbv = 0.0f;
            if (in) {
                float b = pml_b(gi, gj);
                float rb = 1.0f / (4.0f + b);
                float c2v = c2[g];
                P4 = (8.0f - 4.0f * c2v) * rb;   // center coeff
                Qv = (4.0f - b) * rb;            // old-level coeff
                Rcv = c2v * rb;                  // 4-neighbor-sum coeff
                Sbv = msrc[g] * rb;              // source coeff
            }
            cP4[r][i] = P4; cQ[r][i] = Qv; cRc[r][i] = Rcv; cSb[r][i] = Sbv;
            cur[r][i] = 0.0f; old[r][i] = 0.0f;   // initial condition
        }
    }

    volatile unsigned* vbar = &g_bar;

    #pragma unroll 1
    for (int phase = 0; phase < NPHASE; ++phase) {
        const bool even = (phase & 1) == 0;
        const float* rd1 = even ? g_u1a : g_u1b;
        const float* rd2 = even ? g_u2a : g_u2b;
        float* wr1 = even ? g_u1b : g_u1a;
        float* wr2 = even ? g_u2b : g_u2a;
        const int t0 = phase * KSTEP;

        if (tid < KSTEP) sX[tid] = xsrc[t0 + tid];

        // Refresh halo cells from the read pair (in-tile cells carried in regs).
        #pragma unroll
        for (int r = 0; r < 2; ++r)
            #pragma unroll
            for (int i = 0; i < 4; ++i)
                if (!inTile[r][i] && inDom[r][i]) {
                    cur[r][i] = rd1[gidx[r][i]];
                    old[r][i] = rd2[gidx[r][i]];
                }

        // Populate s0 with the current level.
        *(float4*)(s0 + base0) = make_float4(cur[0][0], cur[0][1], cur[0][2], cur[0][3]);
        *(float4*)(s0 + base1) = make_float4(cur[1][0], cur[1][1], cur[1][2], cur[1][3]);
        __syncthreads();

        // ---- KSTEP in-smem steps, fully unrolled, branch-free ----
        #pragma unroll
        for (int s = 0; s < KSTEP; ++s) {
            const float* sc = (s & 1) ? s1 : s0;
            float* sn = (s & 1) ? s0 : s1;
            const float xi = sX[s];

            float4 up = *(const float4*)(sc + base0 - PITCH);
            float4 dn = *(const float4*)(sc + base1 + PITCH);
            float lf0 = sc[base0 - 1], rt0 = sc[base0 + 4];
            float lf1 = sc[base1 - 1], rt1 = sc[base1 + 4];

            float n0[4], n1[4];
            n0[0] = (up.x + cur[1][0]) + (lf0 + cur[0][1]);
            n0[1] = (up.y + cur[1][1]) + (cur[0][0] + cur[0][2]);
            n0[2] = (up.z + cur[1][2]) + (cur[0][1] + cur[0][3]);
            n0[3] = (up.w + cur[1][3]) + (cur[0][2] + rt0);
            n1[0] = (cur[0][0] + dn.x) + (lf1 + cur[1][1]);
            n1[1] = (cur[0][1] + dn.y) + (cur[1][0] + cur[1][2]);
            n1[2] = (cur[0][2] + dn.z) + (cur[1][1] + cur[1][3]);
            n1[3] = (cur[0][3] + dn.w) + (cur[1][2] + rt1);

            float v0[4], v1[4];
            #pragma unroll
            for (int i = 0; i < 4; ++i) {
                float a = cP4[0][i] * cur[0][i];
                a = fmaf(-cQ[0][i], old[0][i], a);
                a = fmaf(cRc[0][i], n0[i], a);
                v0[i] = fmaf(cSb[0][i], xi, a);
                float b = cP4[1][i] * cur[1][i];
                b = fmaf(-cQ[1][i], old[1][i], b);
                b = fmaf(cRc[1][i], n1[i], b);
                v1[i] = fmaf(cSb[1][i], xi, b);
            }

            *(float4*)(sn + base0) = make_float4(v0[0], v0[1], v0[2], v0[3]);
            *(float4*)(sn + base1) = make_float4(v1[0], v1[1], v1[2], v1[3]);

            #pragma unroll
            for (int i = 0; i < 4; ++i) {
                old[0][i] = cur[0][i]; cur[0][i] = v0[i];
                old[1][i] = cur[1][i]; cur[1][i] = v1[i];
            }
            __syncthreads();
        }

        // Write back tile cells (others' halos next phase / final output).
        if (phase == NPHASE - 1) {
            #pragma unroll
            for (int r = 0; r < 2; ++r)
                #pragma unroll
                for (int i = 0; i < 4; ++i)
                    if (inTile[r][i]) d_final[gidx[r][i]] = cur[r][i];
        } else {
            #pragma unroll
            for (int r = 0; r < 2; ++r)
                #pragma unroll
                for (int i = 0; i < 4; ++i)
                    if (inTile[r][i]) {
                        wr1[gidx[r][i]] = cur[r][i];
                        wr2[gidx[r][i]] = old[r][i];
                    }

            // ---- Software grid barrier (all 128 blocks resident) ----
            __syncthreads();
            __threadfence();
            if (tid == 0) {
                unsigned target = (unsigned)NBLK * (unsigned)(phase + 1);
                atomicAdd(&g_bar, 1u);
                while (*vbar < target) { }
            }
            __syncthreads();
            __threadfence();
        }
    }
}

extern "C" void kernel_launch(void* const* d_in, const int* in_sizes, int n_in,
                              void* d_out, int out_size) {
    const float* x    = (const float*)d_in[0];   // (300,)
    const float* c2   = (const float*)d_in[1];   // (512,512)
    const float* msrc = (const float*)d_in[2];   // (512,512)
    float* out = (float*)d_out;

    wave_zero_kernel<<<NCELL / 256, 256>>>();

    dim3 grd(NYg / TJ, NXg / TI);   // (16, 8) = 128 blocks, 1 per SM
    dim3 blk(NGRP, NPAIR);          // (13, 42) = 546 threads
    wave_persist_kernel<<<grd, blk>>>(c2, msrc, x, out);
}

// round 10
// speedup vs baseline: 1.3875x; 1.0306x over previous
#include <cuda_runtime.h>

#define NXg 512
#define NYg 512
#define NTg 300
#define NCELL (NXg * NYg)

#define TI 64                     // tile rows per block
#define TJ 32                     // tile cols per block
#define KSTEP 10
#define NPHASE (NTg / KSTEP)      // 30
#define RI (TI + 2 * KSTEP)       // 84 region rows
#define RJ (TJ + 2 * KSTEP)       // 52 region cols (13 float4 groups)
#define NGRP (RJ / 4)             // 13 column groups
#define NPAIR (RI / 2)            // 42 row pairs
#define PITCH 68                  // floats per smem row (16B aligned, bank-shifted)
#define SROWS (RI + 2)            // 86 rows incl guard top/bottom
#define SSZ (SROWS * PITCH)       // 5848 floats per level
#define COL0 4                    // smem float offset of region col 0
#define NTHR (NGRP * NPAIR)       // 546 threads
#define NBX 16                    // blocks in j
#define NBY 8                     // blocks in i
#define NBLK (NBX * NBY)          // 128 blocks, 1 per SM, all resident

// Ping-pong pairs across phases + per-block phase flags (128B padded).
__device__ float g_u1a[NCELL];
__device__ float g_u2a[NCELL];
__device__ float g_u1b[NCELL];
__device__ float g_u2b[NCELL];
__device__ unsigned g_flags[NBLK * 32];

__global__ void wave_zero_kernel() {
    int idx = blockIdx.x * blockDim.x + threadIdx.x;
    if (idx < NBLK * 32) g_flags[idx] = 0u;
    if (idx < NCELL) {
        g_u1a[idx] = 0.0f;
        g_u2a[idx] = 0.0f;
    }
}

__device__ __forceinline__ void st_release_gpu(unsigned* p, unsigned v) {
    asm volatile("st.release.gpu.global.u32 [%0], %1;" :: "l"(p), "r"(v) : "memory");
}
__device__ __forceinline__ unsigned ld_acquire_gpu(const unsigned* p) {
    unsigned v;
    asm volatile("ld.acquire.gpu.global.u32 %0, [%1];" : "=r"(v) : "l"(p) : "memory");
    return v;
}

// PML ramp: b_vals[k] = 0.5 * (k/20)^3, k in [0,20]
__device__ __forceinline__ float pml_ramp(int k) {
    float t = (float)k * (1.0f / 20.0f);
    return 0.5f * t * t * t;
}

__device__ __forceinline__ float pml_b(int gi, int gj) {
    float bx = 0.0f, by = 0.0f;
    if (gi <= 20) bx = pml_ramp(20 - gi);
    else if (gi >= NXg - 22 && gi <= NXg - 2) bx = pml_ramp(gi - (NXg - 22));
    if (gj <= 20) by = pml_ramp(20 - gj);
    else if (gj >= NYg - 22 && gj <= NYg - 2) by = pml_ramp(gj - (NYg - 22));
    return sqrtf(bx * bx + by * by);
}

__global__ void __launch_bounds__(NTHR)
wave_persist_kernel(const float* __restrict__ c2,
                    const float* __restrict__ msrc,
                    const float* __restrict__ xsrc,
                    float* __restrict__ d_final) {
    __shared__ __align__(16) float s0[SSZ];
    __shared__ __align__(16) float s1[SSZ];
    __shared__ float sX[NTg];
    __shared__ int sNbr[8];
    __shared__ int sNnbr;

    const int tx = threadIdx.x;            // 0..12  column group
    const int ty = threadIdx.y;            // 0..41  row pair
    const int tid = ty * NGRP + tx;

    const int bj = blockIdx.x, bi = blockIdx.y;
    const int gi0 = bi * TI;
    const int gj0 = bj * TJ;
    const int ri0 = gi0 - KSTEP;
    const int rj0 = gj0 - KSTEP;
    const int r0 = 2 * ty;                              // first owned region row
    const int base0 = (r0 + 1) * PITCH + COL0 + 4 * tx;
    const int base1 = base0 + PITCH;

    // Neighbor list (≤8) for the flag handshake.
    if (tid == 0) {
        int n = 0;
        for (int di = -1; di <= 1; ++di)
            for (int dj = -1; dj <= 1; ++dj) {
                if (di == 0 && dj == 0) continue;
                int ni = bi + di, nj = bj + dj;
                if (ni >= 0 && ni < NBY && nj >= 0 && nj < NBX)
                    sNbr[n++] = (ni * NBX + nj) * 32;
            }
        sNnbr = n;
    }

    // Preload the full source series once.
    for (int k = tid; k < NTg; k += NTHR) sX[k] = xsrc[k];

    // Zero both smem levels incl. guards (guards stay 0 forever).
    for (int k = tid; k < SSZ; k += NTHR) { s0[k] = 0.0f; s1[k] = 0.0f; }

    // ---- One-time: coefficients + cell metadata into registers ----
    float cur[2][4], old[2][4];
    float cP4[2][4], cQ[2][4], cRc[2][4], cSb[2][4];
    int gidx[2][4];
    bool inDom[2][4], inTile[2][4];
    #pragma unroll
    for (int r = 0; r < 2; ++r) {
        int rr = r0 + r;
        int gi = ri0 + rr;
        #pragma unroll
        for (int i = 0; i < 4; ++i) {
            int cc = 4 * tx + i;
            int gj = rj0 + cc;
            bool in = ((unsigned)gi < NXg) && ((unsigned)gj < NYg);
            inDom[r][i] = in;
            inTile[r][i] = (rr >= KSTEP) && (rr < KSTEP + TI) &&
                           (cc >= KSTEP) && (cc < KSTEP + TJ);
            int g = in ? (gi * NYg + gj) : 0;
            gidx[r][i] = g;
            float P4 = 0.0f, Qv = 0.0f, Rcv = 0.0f, Sbv = 0.0f;
            if (in) {
                float b = pml_b(gi, gj);
                float rb = 1.0f / (4.0f + b);
                float c2v = c2[g];
                P4 = (8.0f - 4.0f * c2v) * rb;   // center coeff
                Qv = (4.0f - b) * rb;            // old-level coeff
                Rcv = c2v * rb;                  // 4-neighbor-sum coeff
                Sbv = msrc[g] * rb;              // source coeff
            }
            cP4[r][i] = P4; cQ[r][i] = Qv; cRc[r][i] = Rcv; cSb[r][i] = Sbv;
            cur[r][i] = 0.0f; old[r][i] = 0.0f;   // initial condition
        }
    }
    __syncthreads();   // sNbr/sNnbr, sX, smem-zero visible

    unsigned* myFlag = &g_flags[(bi * NBX + bj) * 32];

    #pragma unroll 1
    for (int phase = 0; phase < NPHASE; ++phase) {
        const bool even = (phase & 1) == 0;
        const float* rd1 = even ? g_u1a : g_u1b;
        const float* rd2 = even ? g_u2a : g_u2b;
        float* wr1 = even ? g_u1b : g_u1a;
        float* wr2 = even ? g_u2b : g_u2a;
        const int t0 = phase * KSTEP;

        // Wait for the ≤8 neighbors to have finished phase-1 (flag >= phase).
        if (phase > 0) {
            if (tid < sNnbr) {
                const unsigned* f = &g_flags[sNbr[tid]];
                while (ld_acquire_gpu(f) < (unsigned)phase) { }
            }
            __syncthreads();
        }

        // Refresh halo cells from the read pair (L2-direct; tile cells in regs).
        #pragma unroll
        for (int r = 0; r < 2; ++r)
            #pragma unroll
            for (int i = 0; i < 4; ++i)
                if (!inTile[r][i] && inDom[r][i]) {
                    cur[r][i] = __ldcg(&rd1[gidx[r][i]]);
                    old[r][i] = __ldcg(&rd2[gidx[r][i]]);
                }

        // Populate s0 with the current level.
        *(float4*)(s0 + base0) = make_float4(cur[0][0], cur[0][1], cur[0][2], cur[0][3]);
        *(float4*)(s0 + base1) = make_float4(cur[1][0], cur[1][1], cur[1][2], cur[1][3]);
        __syncthreads();

        // ---- KSTEP in-smem steps, fully unrolled, branch-free ----
        #pragma unroll
        for (int s = 0; s < KSTEP; ++s) {
            const float* sc = (s & 1) ? s1 : s0;
            float* sn = (s & 1) ? s0 : s1;
            const float xi = sX[t0 + s];

            float4 up = *(const float4*)(sc + base0 - PITCH);
            float4 dn = *(const float4*)(sc + base1 + PITCH);
            float lf0 = sc[base0 - 1], rt0 = sc[base0 + 4];
            float lf1 = sc[base1 - 1], rt1 = sc[base1 + 4];

            float n0[4], n1[4];
            n0[0] = (up.x + cur[1][0]) + (lf0 + cur[0][1]);
            n0[1] = (up.y + cur[1][1]) + (cur[0][0] + cur[0][2]);
            n0[2] = (up.z + cur[1][2]) + (cur[0][1] + cur[0][3]);
            n0[3] = (up.w + cur[1][3]) + (cur[0][2] + rt0);
            n1[0] = (cur[0][0] + dn.x) + (lf1 + cur[1][1]);
            n1[1] = (cur[0][1] + dn.y) + (cur[1][0] + cur[1][2]);
            n1[2] = (cur[0][2] + dn.z) + (cur[1][1] + cur[1][3]);
            n1[3] = (cur[0][3] + dn.w) + (cur[1][2] + rt1);

            float v0[4], v1[4];
            #pragma unroll
            for (int i = 0; i < 4; ++i) {
                float a = cP4[0][i] * cur[0][i];
                a = fmaf(-cQ[0][i], old[0][i], a);
                a = fmaf(cRc[0][i], n0[i], a);
                v0[i] = fmaf(cSb[0][i], xi, a);
                float b = cP4[1][i] * cur[1][i];
                b = fmaf(-cQ[1][i], old[1][i], b);
                b = fmaf(cRc[1][i], n1[i], b);
                v1[i] = fmaf(cSb[1][i], xi, b);
            }

            *(float4*)(sn + base0) = make_float4(v0[0], v0[1], v0[2], v0[3]);
            *(float4*)(sn + base1) = make_float4(v1[0], v1[1], v1[2], v1[3]);

            #pragma unroll
            for (int i = 0; i < 4; ++i) {
                old[0][i] = cur[0][i]; cur[0][i] = v0[i];
                old[1][i] = cur[1][i]; cur[1][i] = v1[i];
            }
            __syncthreads();
        }

        // Write back tile cells.
        if (phase == NPHASE - 1) {
            #pragma unroll
            for (int r = 0; r < 2; ++r)
                #pragma unroll
                for (int i = 0; i < 4; ++i)
                    if (inTile[r][i]) d_final[gidx[r][i]] = cur[r][i];
        } else {
            #pragma unroll
            for (int r = 0; r < 2; ++r)
                #pragma unroll
                for (int i = 0; i < 4; ++i)
                    if (inTile[r][i]) {
                        wr1[gidx[r][i]] = cur[r][i];
                        wr2[gidx[r][i]] = old[r][i];
                    }
            // Publish: all threads' stores ordered via bar, then release by tid0.
            __syncthreads();
            if (tid == 0) st_release_gpu(myFlag, (unsigned)(phase + 1));
        }
    }
}

extern "C" void kernel_launch(void* const* d_in, const int* in_sizes, int n_in,
                              void* d_out, int out_size) {
    const float* x    = (const float*)d_in[0];   // (300,)
    const float* c2   = (const float*)d_in[1];   // (512,512)
    const float* msrc = (const float*)d_in[2];   // (512,512)
    float* out = (float*)d_out;

    wave_zero_kernel<<<NCELL / 256, 256>>>();

    dim3 grd(NBX, NBY);             // (16, 8) = 128 blocks, 1 per SM
    dim3 blk(NGRP, NPAIR);          // (13, 42) = 546 threads
    wave_persist_kernel<<<grd, blk>>>(c2, msrc, x, out);
}